// round 8
// baseline (speedup 1.0000x reference)
#include <cuda_runtime.h>
#include <math.h>
#include <stdint.h>

#define BATCH 2
#define SEQ   2048
#define DMODEL 2048
#define NHEAD 16
#define DHEAD 128
#define D3    (3*DMODEL)
#define KDIM  2048

// Scratch (device globals — no allocation allowed)
__device__ float g_qkv[(size_t)BATCH * SEQ * D3];        // [B,S,3D]
__device__ float g_attn[(size_t)BATCH * SEQ * DMODEL];   // [B,S,D] (tf32-rounded)
__device__ float g_xr[(size_t)BATCH * SEQ * DMODEL];     // x tf32-rounded
__device__ float g_wt[(size_t)DMODEL * D3 + (size_t)DMODEL * DMODEL]; // W rounded
__device__ float g_cos[SEQ * 64];
__device__ float g_sin[SEQ * 64];

__device__ __forceinline__ float tf32r(float x) {
    float r;
    asm("cvt.rna.tf32.f32 %0, %1;" : "=f"(r) : "f"(x));
    return r;
}
__device__ __forceinline__ uint32_t smem_u32(const void* p) {
    uint32_t a;
    asm("{ .reg .u64 t; cvta.to.shared.u64 t, %1; cvt.u32.u64 %0, t; }"
        : "=r"(a) : "l"(p));
    return a;
}
__device__ __forceinline__ void cp_async16(uint32_t dst, const void* src) {
    asm volatile("cp.async.cg.shared.global [%0], [%1], 16;"
                 :: "r"(dst), "l"(src));
}
#define CP_COMMIT() asm volatile("cp.async.commit_group;" ::: "memory")
#define CP_WAIT(n)  asm volatile("cp.async.wait_group %0;" :: "n"(n) : "memory")

__device__ __forceinline__ void mma_tf32(float& d0, float& d1, float& d2, float& d3,
                                         uint32_t a0, uint32_t a1, uint32_t a2, uint32_t a3,
                                         uint32_t b0, uint32_t b1) {
    asm volatile(
        "mma.sync.aligned.m16n8k8.row.col.f32.tf32.tf32.f32 "
        "{%0,%1,%2,%3}, {%4,%5,%6,%7}, {%8,%9}, {%0,%1,%2,%3};"
        : "+f"(d0), "+f"(d1), "+f"(d2), "+f"(d3)
        : "r"(a0), "r"(a1), "r"(a2), "r"(a3), "r"(b0), "r"(b1));
}

// ===========================================================================
// Elementwise tf32 pre-round (rna), float4 vectorized
// ===========================================================================
__global__ void round_tf32_kernel(const float* __restrict__ in,
                                  float* __restrict__ out, int n4) {
    int i = blockIdx.x * blockDim.x + threadIdx.x;
    if (i >= n4) return;
    float4 v = ((const float4*)in)[i];
    float4 o;
    o.x = tf32r(v.x); o.y = tf32r(v.y); o.z = tf32r(v.z); o.w = tf32r(v.w);
    ((float4*)out)[i] = o;
}

// ===========================================================================
// cp.async 4-stage tf32 GEMM: C[M,N] = A[M,2048] @ W[2048,N] + bias[N]
// Inputs pre-rounded to tf32. CTA tile 128x128, BK=32, 256 threads.
//   A smem [128][AS=36], B smem [32][BS=136]  (conflict-free frag reads)
// ===========================================================================
#define BK 32
#define NT (KDIM / BK)
#define AS 36
#define BS 136
#define A_STG (128 * AS)
#define B_STG (32 * BS)
#define STG_FLOATS (A_STG + B_STG)          // 8960 floats = 35840 B
#define NSTG 4
#define GEMM_SMEM (NSTG * STG_FLOATS * 4)   // 143360 B

__global__ void __launch_bounds__(256, 1)
gemm_ca_kernel(const float* __restrict__ A, const float* __restrict__ W,
               const float* __restrict__ bias, float* __restrict__ C, int N) {
    extern __shared__ float smem[];
    const uint32_t smem_u = smem_u32(smem);

    const int tid  = threadIdx.x;
    const int lane = tid & 31;
    const int warp = tid >> 5;
    const int wm   = warp >> 1;
    const int wn   = warp & 1;
    const int grp  = lane >> 2;
    const int tig  = lane & 3;
    const int brow = blockIdx.y;
    const int bcol = blockIdx.x;

    const int ar  = tid >> 3;
    const int ac4 = tid & 7;
    const int bk  = tid >> 5;
    const int bc4 = tid & 31;

    const float* Ag = A + (size_t)(brow * 128 + ar) * KDIM + ac4 * 4;
    const float* Wg = W + (size_t)bk * N + bcol * 128 + bc4 * 4;

    // Precomputed smem dst offsets (bytes, per stage base)
    uint32_t a_dst[4], b_dst[4];
#pragma unroll
    for (int i = 0; i < 4; i++) {
        a_dst[i] = ((ar + i * 32) * AS + ac4 * 4) * 4;
        b_dst[i] = (A_STG + (bk + i * 8) * BS + bc4 * 4) * 4;
    }

    auto issue = [&](int j) {
        uint32_t sbase = smem_u + (j & (NSTG - 1)) * (STG_FLOATS * 4);
        int k0 = j * BK;
#pragma unroll
        for (int i = 0; i < 4; i++)
            cp_async16(sbase + a_dst[i], Ag + (size_t)(i * 32) * KDIM + k0);
#pragma unroll
        for (int i = 0; i < 4; i++)
            cp_async16(sbase + b_dst[i], Wg + (size_t)(k0 + i * 8) * N);
        CP_COMMIT();
    };

    float acc[2][8][4];
#pragma unroll
    for (int m = 0; m < 2; m++)
#pragma unroll
        for (int n = 0; n < 8; n++)
#pragma unroll
            for (int c = 0; c < 4; c++) acc[m][n][c] = 0.f;

    issue(0); issue(1); issue(2);

    const int rb0 = wm * 32 + grp;
    const int cb0 = wn * 64 + grp;

    for (int j = 0; j < NT; j++) {
        CP_WAIT(2);
        __syncthreads();

        const float* sa = smem + (j & (NSTG - 1)) * STG_FLOATS;
        const float* sb = sa + A_STG;
#pragma unroll
        for (int ks = 0; ks < 4; ks++) {
            int kc = ks * 8 + tig;
            uint32_t af[2][4];
#pragma unroll
            for (int m = 0; m < 2; m++) {
                const float* ap = sa + (rb0 + m * 16) * AS + kc;
                af[m][0] = __float_as_uint(ap[0]);
                af[m][1] = __float_as_uint(ap[8 * AS]);
                af[m][2] = __float_as_uint(ap[4]);
                af[m][3] = __float_as_uint(ap[8 * AS + 4]);
            }
            uint32_t bf[8][2];
            const float* bp = sb + kc * BS + cb0;
#pragma unroll
            for (int n = 0; n < 8; n++) {
                bf[n][0] = __float_as_uint(bp[n * 8]);
                bf[n][1] = __float_as_uint(bp[4 * BS + n * 8]);
            }
#pragma unroll
            for (int m = 0; m < 2; m++)
#pragma unroll
                for (int n = 0; n < 8; n++)
                    mma_tf32(acc[m][n][0], acc[m][n][1], acc[m][n][2], acc[m][n][3],
                             af[m][0], af[m][1], af[m][2], af[m][3],
                             bf[n][0], bf[n][1]);
        }

        if (j + 3 < NT) issue(j + 3);
    }

    // Epilogue
#pragma unroll
    for (int m = 0; m < 2; m++) {
        int row0 = brow * 128 + wm * 32 + m * 16 + grp;
#pragma unroll
        for (int n = 0; n < 8; n++) {
            int col = bcol * 128 + wn * 64 + n * 8 + tig * 2;
            float2 bv = *(const float2*)(bias + col);
            float2 o0, o1;
            o0.x = acc[m][n][0] + bv.x; o0.y = acc[m][n][1] + bv.y;
            o1.x = acc[m][n][2] + bv.x; o1.y = acc[m][n][3] + bv.y;
            *(float2*)(C + (size_t)row0 * N + col)       = o0;
            *(float2*)(C + (size_t)(row0 + 8) * N + col) = o1;
        }
    }
}

// ===========================================================================
// RoPE
// ===========================================================================
__global__ void rope_table_kernel() {
    int idx = blockIdx.x * blockDim.x + threadIdx.x;
    if (idx >= SEQ * 64) return;
    int s = idx >> 6;
    int i = idx & 63;
    double theta = exp(-(double)i * log(10000.0) / 64.0);
    float tf = (float)theta;
    float ang = (float)s * tf;
    g_cos[idx] = (float)cos((double)ang);
    g_sin[idx] = (float)sin((double)ang);
}

__global__ void rope_apply_kernel() {
    int idx = blockIdx.x * blockDim.x + threadIdx.x;
    int i = idx & 63;
    int h = (idx >> 6) & (NHEAD - 1);
    int s = (idx >> 10) & (SEQ - 1);
    int b = idx >> 21;
    if (b >= BATCH) return;

    float c  = g_cos[s * 64 + i];
    float sn = g_sin[s * 64 + i];

    size_t base = ((size_t)(b * SEQ + s)) * D3 + h * DHEAD;
    float* q = g_qkv + base;
    float* k = g_qkv + base + DMODEL;

    float q0 = q[i], q1 = q[i + 64];
    q[i]      = c * q0 - sn * q1;
    q[i + 64] = c * q1 + sn * q0;

    float k0 = k[i], k1 = k[i + 64];
    k[i]      = c * k0 - sn * k1;
    k[i + 64] = c * k1 + sn * k0;
}

// ===========================================================================
// Flash attention on mma.sync tf32 (round-7 known-good; output tf32-rounded)
// ===========================================================================
#define QS_PAD 132
#define KS_PAD 132
#define VS_PAD 136
#define PS_PAD 132
#define QS_OFF 0
#define KS_OFF (64 * QS_PAD)
#define VS_OFF (KS_OFF + 128 * KS_PAD)
#define PS_OFF (VS_OFF + 128 * VS_PAD)
#define PM_OFF (PS_OFF + 64 * PS_PAD)
#define PL_OFF (PM_OFF + 128)
#define ATT_SMEM_FLOATS (PL_OFF + 128)

__global__ void __launch_bounds__(256, 1)
attn_mma_kernel(const float* __restrict__ qkv, float* __restrict__ out) {
    extern __shared__ float sm[];
    float* Qs = sm + QS_OFF;
    float* Ks = sm + KS_OFF;
    float* Vs = sm + VS_OFF;
    float* Ps = sm + PS_OFF;
    float* pm = sm + PM_OFF;
    float* pl = sm + PL_OFF;

    const float SCALE = 0.08838834764831845f;
    const float NEG_BIG = -3.0e38f;

    const int qt = blockIdx.x, h = blockIdx.y, b = blockIdx.z;
    const int tid = threadIdx.x;
    const int lane = tid & 31, warp = tid >> 5;
    const int grp = lane >> 2, tig = lane & 3;
    const int qg = warp & 3, half = warp >> 2;
    const int n0 = half * 64;

    const float* qbase = qkv + (size_t)(b * SEQ) * D3 + h * DHEAD;
    const float* kbase = qbase + DMODEL;
    const float* vbase = qbase + 2 * DMODEL;

    const int qrow0 = qt * 64;
    const int r_lo = qg * 16 + grp;
    const int r_hi = r_lo + 8;

#pragma unroll
    for (int t = 0; t < 8; t++) {
        int lin = tid + t * 256;
        int row = lin >> 5;
        int d0 = (lin & 31) * 4;
        float4 v = *(const float4*)(qbase + (size_t)(qrow0 + row) * D3 + d0);
        float4 o;
        o.x = tf32r(v.x * SCALE); o.y = tf32r(v.y * SCALE);
        o.z = tf32r(v.z * SCALE); o.w = tf32r(v.w * SCALE);
        *(float4*)(Qs + row * QS_PAD + d0) = o;
    }

    float oacc[8][4];
#pragma unroll
    for (int j = 0; j < 8; j++)
#pragma unroll
        for (int c = 0; c < 4; c++) oacc[j][c] = 0.f;

    float m_lo = NEG_BIG, m_hi = NEG_BIG;
    float l_lo = 0.f, l_hi = 0.f;

    const int nkt = (qt >> 1) + 1;

    for (int kt = 0; kt < nkt; kt++) {
        const int key0 = kt * 128;
        const int doff = qt * 64 - key0;

        __syncthreads();

#pragma unroll
        for (int t = 0; t < 16; t++) {
            int lin = tid + t * 256;
            int row = lin >> 5;
            int d0 = (lin & 31) * 4;
            size_t goff = (size_t)(key0 + row) * D3 + d0;
            float4 kv = *(const float4*)(kbase + goff);
            float4 ko;
            ko.x = tf32r(kv.x); ko.y = tf32r(kv.y);
            ko.z = tf32r(kv.z); ko.w = tf32r(kv.w);
            *(float4*)(Ks + row * KS_PAD + d0) = ko;
            float4 vv = *(const float4*)(vbase + goff);
            float4 vo;
            vo.x = tf32r(vv.x); vo.y = tf32r(vv.y);
            vo.z = tf32r(vv.z); vo.w = tf32r(vv.w);
            *(float4*)(Vs + row * VS_PAD + d0) = vo;
        }
        __syncthreads();

        float sacc[8][4];
#pragma unroll
        for (int j = 0; j < 8; j++)
#pragma unroll
            for (int c = 0; c < 4; c++) sacc[j][c] = 0.f;

        const float* qpA = Qs + r_lo * QS_PAD;
        const float* kpB = Ks + (n0 + grp) * KS_PAD;
#pragma unroll 4
        for (int ks = 0; ks < 16; ks++) {
            int kc = ks * 8 + tig;
            uint32_t a0 = __float_as_uint(qpA[kc]);
            uint32_t a1 = __float_as_uint(qpA[8 * QS_PAD + kc]);
            uint32_t a2 = __float_as_uint(qpA[kc + 4]);
            uint32_t a3 = __float_as_uint(qpA[8 * QS_PAD + kc + 4]);
#pragma unroll
            for (int j = 0; j < 8; j++) {
                uint32_t b0 = __float_as_uint(kpB[j * 8 * KS_PAD + kc]);
                uint32_t b1 = __float_as_uint(kpB[j * 8 * KS_PAD + kc + 4]);
                mma_tf32(sacc[j][0], sacc[j][1], sacc[j][2], sacc[j][3],
                         a0, a1, a2, a3, b0, b1);
            }
        }

        float pmax_lo = NEG_BIG, pmax_hi = NEG_BIG;
#pragma unroll
        for (int j = 0; j < 8; j++) {
            int c0 = n0 + j * 8 + 2 * tig;
            if (c0     <= r_lo + doff) pmax_lo = fmaxf(pmax_lo, sacc[j][0]);
            if (c0 + 1 <= r_lo + doff) pmax_lo = fmaxf(pmax_lo, sacc[j][1]);
            if (c0     <= r_hi + doff) pmax_hi = fmaxf(pmax_hi, sacc[j][2]);
            if (c0 + 1 <= r_hi + doff) pmax_hi = fmaxf(pmax_hi, sacc[j][3]);
        }
        pmax_lo = fmaxf(pmax_lo, __shfl_xor_sync(0xFFFFFFFF, pmax_lo, 1));
        pmax_lo = fmaxf(pmax_lo, __shfl_xor_sync(0xFFFFFFFF, pmax_lo, 2));
        pmax_hi = fmaxf(pmax_hi, __shfl_xor_sync(0xFFFFFFFF, pmax_hi, 1));
        pmax_hi = fmaxf(pmax_hi, __shfl_xor_sync(0xFFFFFFFF, pmax_hi, 2));
        if (tig == 0) {
            pm[half * 64 + r_lo] = pmax_lo;
            pm[half * 64 + r_hi] = pmax_hi;
        }
        __syncthreads();

        float mn_lo = fmaxf(m_lo, fmaxf(pm[r_lo], pm[64 + r_lo]));
        float mn_hi = fmaxf(m_hi, fmaxf(pm[r_hi], pm[64 + r_hi]));
        float al_lo = __expf(m_lo - mn_lo);
        float al_hi = __expf(m_hi - mn_hi);
        m_lo = mn_lo; m_hi = mn_hi;

        float sum_lo = 0.f, sum_hi = 0.f;
#pragma unroll
        for (int j = 0; j < 8; j++) {
            int c0 = n0 + j * 8 + 2 * tig;
            float p0 = (c0     <= r_lo + doff) ? __expf(sacc[j][0] - mn_lo) : 0.f;
            float p1 = (c0 + 1 <= r_lo + doff) ? __expf(sacc[j][1] - mn_lo) : 0.f;
            float p2 = (c0     <= r_hi + doff) ? __expf(sacc[j][2] - mn_hi) : 0.f;
            float p3 = (c0 + 1 <= r_hi + doff) ? __expf(sacc[j][3] - mn_hi) : 0.f;
            sum_lo += p0 + p1;
            sum_hi += p2 + p3;
            float2 v01; v01.x = tf32r(p0); v01.y = tf32r(p1);
            float2 v23; v23.x = tf32r(p2); v23.y = tf32r(p3);
            *(float2*)(Ps + r_lo * PS_PAD + c0) = v01;
            *(float2*)(Ps + r_hi * PS_PAD + c0) = v23;
        }
        sum_lo += __shfl_xor_sync(0xFFFFFFFF, sum_lo, 1);
        sum_lo += __shfl_xor_sync(0xFFFFFFFF, sum_lo, 2);
        sum_hi += __shfl_xor_sync(0xFFFFFFFF, sum_hi, 1);
        sum_hi += __shfl_xor_sync(0xFFFFFFFF, sum_hi, 2);
        if (tig == 0) {
            pl[half * 64 + r_lo] = sum_lo;
            pl[half * 64 + r_hi] = sum_hi;
        }
        __syncthreads();

        l_lo = l_lo * al_lo + pl[r_lo] + pl[64 + r_lo];
        l_hi = l_hi * al_hi + pl[r_hi] + pl[64 + r_hi];
#pragma unroll
        for (int j = 0; j < 8; j++) {
            oacc[j][0] *= al_lo; oacc[j][1] *= al_lo;
            oacc[j][2] *= al_hi; oacc[j][3] *= al_hi;
        }

        const float* ppA = Ps + r_lo * PS_PAD;
#pragma unroll 4
        for (int ks = 0; ks < 16; ks++) {
            int kc = ks * 8 + tig;
            uint32_t a0 = __float_as_uint(ppA[kc]);
            uint32_t a1 = __float_as_uint(ppA[8 * PS_PAD + kc]);
            uint32_t a2 = __float_as_uint(ppA[kc + 4]);
            uint32_t a3 = __float_as_uint(ppA[8 * PS_PAD + kc + 4]);
            const float* vpB = Vs + kc * VS_PAD + n0 + grp;
#pragma unroll
            for (int j = 0; j < 8; j++) {
                uint32_t b0 = __float_as_uint(vpB[j * 8]);
                uint32_t b1 = __float_as_uint(vpB[4 * VS_PAD + j * 8]);
                mma_tf32(oacc[j][0], oacc[j][1], oacc[j][2], oacc[j][3],
                         a0, a1, a2, a3, b0, b1);
            }
        }
    }

    // normalize + store (tf32-rounded so out-proj can skip cvt)
    float inv_lo = 1.f / l_lo;
    float inv_hi = 1.f / l_hi;
    float* obase = out + (size_t)(b * SEQ + qrow0) * DMODEL + h * DHEAD;
#pragma unroll
    for (int j = 0; j < 8; j++) {
        int col = n0 + j * 8 + 2 * tig;
        float2 o0, o1;
        o0.x = tf32r(oacc[j][0] * inv_lo); o0.y = tf32r(oacc[j][1] * inv_lo);
        o1.x = tf32r(oacc[j][2] * inv_hi); o1.y = tf32r(oacc[j][3] * inv_hi);
        *(float2*)(obase + (size_t)r_lo * DMODEL + col) = o0;
        *(float2*)(obase + (size_t)r_hi * DMODEL + col) = o1;
    }
}

// ===========================================================================
// Launch
// ===========================================================================
extern "C" void kernel_launch(void* const* d_in, const int* in_sizes, int n_in,
                              void* d_out, int out_size) {
    const float* x     = (const float*)d_in[0];
    const float* w_in  = (const float*)d_in[2];
    const float* b_in  = (const float*)d_in[3];
    const float* w_out = (const float*)d_in[4];
    const float* b_out = (const float*)d_in[5];
    float* out = (float*)d_out;

    float* qkv;   cudaGetSymbolAddress((void**)&qkv,  g_qkv);
    float* attn;  cudaGetSymbolAddress((void**)&attn, g_attn);
    float* xr;    cudaGetSymbolAddress((void**)&xr,   g_xr);
    float* wt;    cudaGetSymbolAddress((void**)&wt,   g_wt);
    float* wt_in  = wt;
    float* wt_out = wt + (size_t)DMODEL * D3;

    cudaFuncSetAttribute(attn_mma_kernel,
                         cudaFuncAttributeMaxDynamicSharedMemorySize,
                         ATT_SMEM_FLOATS * (int)sizeof(float));
    cudaFuncSetAttribute(gemm_ca_kernel,
                         cudaFuncAttributeMaxDynamicSharedMemorySize,
                         GEMM_SMEM);

    // 0. Pre-round x, W_in, W_out to tf32 (rna)
    {
        int n4x = (BATCH * SEQ * DMODEL) / 4;
        round_tf32_kernel<<<(n4x + 255) / 256, 256>>>(x, xr, n4x);
        int n4wi = (DMODEL * D3) / 4;
        round_tf32_kernel<<<(n4wi + 255) / 256, 256>>>(w_in, wt_in, n4wi);
        int n4wo = (DMODEL * DMODEL) / 4;
        round_tf32_kernel<<<(n4wo + 255) / 256, 256>>>(w_out, wt_out, n4wo);
    }

    // 1. RoPE tables
    rope_table_kernel<<<(SEQ * 64 + 255) / 256, 256>>>();

    // 2. QKV projection (cp.async tf32 GEMM)
    gemm_ca_kernel<<<dim3(D3 / 128, (BATCH * SEQ) / 128), 256, GEMM_SMEM>>>(
        xr, wt_in, b_in, qkv, D3);

    // 3. RoPE in-place on q,k
    rope_apply_kernel<<<(BATCH * SEQ * NHEAD * 64) / 256, 256>>>();

    // 4. Flash attention (mma.sync tf32; writes rounded output)
    attn_mma_kernel<<<dim3(SEQ / 64, NHEAD, BATCH), 256,
                      ATT_SMEM_FLOATS * sizeof(float)>>>(qkv, attn);

    // 5. Output projection (cp.async tf32 GEMM)
    gemm_ca_kernel<<<dim3(DMODEL / 128, (BATCH * SEQ) / 128), 256, GEMM_SMEM>>>(
        attn, wt_out, b_out, out, DMODEL);
}

// round 9
// speedup vs baseline: 1.3454x; 1.3454x over previous
#include <cuda_runtime.h>
#include <math.h>
#include <stdint.h>

#define BATCH 2
#define SEQ   2048
#define DMODEL 2048
#define NHEAD 16
#define DHEAD 128
#define D3    (3*DMODEL)
#define KDIM  2048

// Scratch (device globals — no allocation allowed)
__device__ float g_qkv[(size_t)BATCH * SEQ * D3];        // [B,S,3D]
__device__ float g_attn[(size_t)BATCH * SEQ * DMODEL];   // [B,S,D]
__device__ float g_cos[SEQ * 64];
__device__ float g_sin[SEQ * 64];

__device__ __forceinline__ uint32_t f2tf32(float x) {
    uint32_t r;
    asm("cvt.rna.tf32.f32 %0, %1;" : "=r"(r) : "f"(x));
    return r;
}
__device__ __forceinline__ float tf32r(float x) {
    float r;
    asm("cvt.rna.tf32.f32 %0, %1;" : "=f"(r) : "f"(x));
    return r;
}

__device__ __forceinline__ void mma_tf32(float& d0, float& d1, float& d2, float& d3,
                                         uint32_t a0, uint32_t a1, uint32_t a2, uint32_t a3,
                                         uint32_t b0, uint32_t b1) {
    asm volatile(
        "mma.sync.aligned.m16n8k8.row.col.f32.tf32.tf32.f32 "
        "{%0,%1,%2,%3}, {%4,%5,%6,%7}, {%8,%9}, {%0,%1,%2,%3};"
        : "+f"(d0), "+f"(d1), "+f"(d2), "+f"(d3)
        : "r"(a0), "r"(a1), "r"(a2), "r"(a3), "r"(b0), "r"(b1));
}

// ===========================================================================
// mma.sync tf32 GEMM (round-7 exact — known good at 1579us total)
// ===========================================================================
#define BK 32
#define NT (KDIM / BK)
#define AS 36
#define BS 136
#define A_STG (128 * AS)
#define B_STG (32 * BS)
#define STG_FLOATS (A_STG + B_STG)
#define GEMM_SMEM (2 * STG_FLOATS * 4)

__global__ void __launch_bounds__(256, 1)
mma_gemm_kernel(const float* __restrict__ A, const float* __restrict__ W,
                const float* __restrict__ bias, float* __restrict__ C, int N) {
    extern __shared__ float smem[];

    const int tid  = threadIdx.x;
    const int lane = tid & 31;
    const int warp = tid >> 5;
    const int wm   = warp >> 1;
    const int wn   = warp & 1;
    const int grp  = lane >> 2;
    const int tig  = lane & 3;
    const int brow = blockIdx.y;
    const int bcol = blockIdx.x;

    const int ar  = tid >> 3;
    const int ac4 = tid & 7;
    const int bk  = tid >> 5;
    const int bc4 = tid & 31;

    const float* Ag = A + (size_t)(brow * 128 + ar) * KDIM + ac4 * 4;
    const float* Wg = W + (size_t)bk * N + bcol * 128 + bc4 * 4;

    float4 bufA[4], bufB[4];

    auto ldg_chunk = [&](int j) {
        int k0 = j * BK;
#pragma unroll
        for (int i = 0; i < 4; i++)
            bufA[i] = *(const float4*)(Ag + (size_t)(i * 32) * KDIM + k0);
#pragma unroll
        for (int i = 0; i < 4; i++)
            bufB[i] = *(const float4*)(Wg + (size_t)(k0 + i * 8) * N);
    };

    auto sts_chunk = [&](int s) {
        float* sa = smem + s * STG_FLOATS;
        float* sb = sa + A_STG;
#pragma unroll
        for (int i = 0; i < 4; i++) {
            uint4 v;
            v.x = f2tf32(bufA[i].x); v.y = f2tf32(bufA[i].y);
            v.z = f2tf32(bufA[i].z); v.w = f2tf32(bufA[i].w);
            *(uint4*)(sa + (ar + i * 32) * AS + ac4 * 4) = v;
        }
#pragma unroll
        for (int i = 0; i < 4; i++) {
            uint4 v;
            v.x = f2tf32(bufB[i].x); v.y = f2tf32(bufB[i].y);
            v.z = f2tf32(bufB[i].z); v.w = f2tf32(bufB[i].w);
            *(uint4*)(sb + (bk + i * 8) * BS + bc4 * 4) = v;
        }
    };

    float acc[2][8][4];
#pragma unroll
    for (int m = 0; m < 2; m++)
#pragma unroll
        for (int n = 0; n < 8; n++)
#pragma unroll
            for (int c = 0; c < 4; c++) acc[m][n][c] = 0.f;

    ldg_chunk(0);
    sts_chunk(0);
    __syncthreads();

    const int rb0 = wm * 32 + grp;
    const int cb0 = wn * 64 + grp;

    for (int j = 0; j < NT; j++) {
        if (j + 1 < NT) ldg_chunk(j + 1);

        const float* sa = smem + (j & 1) * STG_FLOATS;
        const float* sb = sa + A_STG;
#pragma unroll
        for (int ks = 0; ks < 4; ks++) {
            int kc = ks * 8 + tig;
            uint32_t af[2][4];
#pragma unroll
            for (int m = 0; m < 2; m++) {
                const float* ap = sa + (rb0 + m * 16) * AS + kc;
                af[m][0] = __float_as_uint(ap[0]);
                af[m][1] = __float_as_uint(ap[8 * AS]);
                af[m][2] = __float_as_uint(ap[4]);
                af[m][3] = __float_as_uint(ap[8 * AS + 4]);
            }
            uint32_t bf[8][2];
            const float* bp = sb + kc * BS + cb0;
#pragma unroll
            for (int n = 0; n < 8; n++) {
                bf[n][0] = __float_as_uint(bp[n * 8]);
                bf[n][1] = __float_as_uint(bp[4 * BS + n * 8]);
            }
#pragma unroll
            for (int m = 0; m < 2; m++)
#pragma unroll
                for (int n = 0; n < 8; n++)
                    mma_tf32(acc[m][n][0], acc[m][n][1], acc[m][n][2], acc[m][n][3],
                             af[m][0], af[m][1], af[m][2], af[m][3],
                             bf[n][0], bf[n][1]);
        }

        if (j + 1 < NT) sts_chunk((j + 1) & 1);
        __syncthreads();
    }

#pragma unroll
    for (int m = 0; m < 2; m++) {
        int row0 = brow * 128 + wm * 32 + m * 16 + grp;
#pragma unroll
        for (int n = 0; n < 8; n++) {
            int col = bcol * 128 + wn * 64 + n * 8 + tig * 2;
            float2 bv = *(const float2*)(bias + col);
            float2 o0, o1;
            o0.x = acc[m][n][0] + bv.x; o0.y = acc[m][n][1] + bv.y;
            o1.x = acc[m][n][2] + bv.x; o1.y = acc[m][n][3] + bv.y;
            *(float2*)(C + (size_t)row0 * N + col)       = o0;
            *(float2*)(C + (size_t)(row0 + 8) * N + col) = o1;
        }
    }
}

// ===========================================================================
// RoPE
// ===========================================================================
__global__ void rope_table_kernel() {
    int idx = blockIdx.x * blockDim.x + threadIdx.x;
    if (idx >= SEQ * 64) return;
    int s = idx >> 6;
    int i = idx & 63;
    double theta = exp(-(double)i * log(10000.0) / 64.0);
    float tf = (float)theta;
    float ang = (float)s * tf;
    g_cos[idx] = (float)cos((double)ang);
    g_sin[idx] = (float)sin((double)ang);
}

// Applies RoPE AND pre-bakes attention input conversions:
//   q <- tf32r(SCALE * rope(q)),  k <- tf32r(rope(k)),  v <- tf32r(v)
__global__ void rope_apply_kernel() {
    const float SCALE = 0.08838834764831845f;  // 1/sqrt(128)
    int idx = blockIdx.x * blockDim.x + threadIdx.x;
    int i = idx & 63;
    int h = (idx >> 6) & (NHEAD - 1);
    int s = (idx >> 10) & (SEQ - 1);
    int b = idx >> 21;
    if (b >= BATCH) return;

    float c  = g_cos[s * 64 + i];
    float sn = g_sin[s * 64 + i];

    size_t base = ((size_t)(b * SEQ + s)) * D3 + h * DHEAD;
    float* q = g_qkv + base;
    float* k = g_qkv + base + DMODEL;
    float* v = g_qkv + base + 2 * DMODEL;

    float q0 = q[i], q1 = q[i + 64];
    q[i]      = tf32r(SCALE * (c * q0 - sn * q1));
    q[i + 64] = tf32r(SCALE * (c * q1 + sn * q0));

    float k0 = k[i], k1 = k[i + 64];
    k[i]      = tf32r(c * k0 - sn * k1);
    k[i + 64] = tf32r(c * k1 + sn * k0);

    v[i]      = tf32r(v[i]);
    v[i + 64] = tf32r(v[i + 64]);
}

// ===========================================================================
// Flash attention on mma.sync tf32. Inputs pre-rounded/prescaled by RoPE pass,
// so all tile loads are plain copies. qt order reversed for tail balance.
// ===========================================================================
#define QS_PAD 132
#define KS_PAD 132
#define VS_PAD 136
#define PS_PAD 132
#define QS_OFF 0
#define KS_OFF (64 * QS_PAD)
#define VS_OFF (KS_OFF + 128 * KS_PAD)
#define PS_OFF (VS_OFF + 128 * VS_PAD)
#define PM_OFF (PS_OFF + 64 * PS_PAD)
#define PL_OFF (PM_OFF + 128)
#define ATT_SMEM_FLOATS (PL_OFF + 128)

__global__ void __launch_bounds__(256, 1)
attn_mma_kernel(const float* __restrict__ qkv, float* __restrict__ out) {
    extern __shared__ float sm[];
    float* Qs = sm + QS_OFF;
    float* Ks = sm + KS_OFF;
    float* Vs = sm + VS_OFF;
    float* Ps = sm + PS_OFF;
    float* pm = sm + PM_OFF;
    float* pl = sm + PL_OFF;

    const float NEG_BIG = -3.0e38f;

    const int qt = (int)gridDim.x - 1 - (int)blockIdx.x;  // big tiles first
    const int h = blockIdx.y, b = blockIdx.z;
    const int tid = threadIdx.x;
    const int lane = tid & 31, warp = tid >> 5;
    const int grp = lane >> 2, tig = lane & 3;
    const int qg = warp & 3, half = warp >> 2;
    const int n0 = half * 64;

    const float* qbase = qkv + (size_t)(b * SEQ) * D3 + h * DHEAD;
    const float* kbase = qbase + DMODEL;
    const float* vbase = qbase + 2 * DMODEL;

    const int qrow0 = qt * 64;
    const int r_lo = qg * 16 + grp;
    const int r_hi = r_lo + 8;

    // Load Q (already scaled + tf32-rounded)
#pragma unroll
    for (int t = 0; t < 8; t++) {
        int lin = tid + t * 256;
        int row = lin >> 5;
        int d0 = (lin & 31) * 4;
        float4 v = *(const float4*)(qbase + (size_t)(qrow0 + row) * D3 + d0);
        *(float4*)(Qs + row * QS_PAD + d0) = v;
    }

    float oacc[8][4];
#pragma unroll
    for (int j = 0; j < 8; j++)
#pragma unroll
        for (int c = 0; c < 4; c++) oacc[j][c] = 0.f;

    float m_lo = NEG_BIG, m_hi = NEG_BIG;
    float l_lo = 0.f, l_hi = 0.f;

    const int nkt = (qt >> 1) + 1;

    for (int kt = 0; kt < nkt; kt++) {
        const int key0 = kt * 128;
        const int doff = qt * 64 - key0;

        __syncthreads();

        // Load K,V tile [128][128] (pre-rounded)
#pragma unroll
        for (int t = 0; t < 16; t++) {
            int lin = tid + t * 256;
            int row = lin >> 5;
            int d0 = (lin & 31) * 4;
            size_t goff = (size_t)(key0 + row) * D3 + d0;
            float4 kv = *(const float4*)(kbase + goff);
            *(float4*)(Ks + row * KS_PAD + d0) = kv;
            float4 vv = *(const float4*)(vbase + goff);
            *(float4*)(Vs + row * VS_PAD + d0) = vv;
        }
        __syncthreads();

        // ---- S = Q @ K^T on this warp's key half ----
        float sacc[8][4];
#pragma unroll
        for (int j = 0; j < 8; j++)
#pragma unroll
            for (int c = 0; c < 4; c++) sacc[j][c] = 0.f;

        const float* qpA = Qs + r_lo * QS_PAD;
        const float* kpB = Ks + (n0 + grp) * KS_PAD;
#pragma unroll 4
        for (int ks = 0; ks < 16; ks++) {
            int kc = ks * 8 + tig;
            uint32_t a0 = __float_as_uint(qpA[kc]);
            uint32_t a1 = __float_as_uint(qpA[8 * QS_PAD + kc]);
            uint32_t a2 = __float_as_uint(qpA[kc + 4]);
            uint32_t a3 = __float_as_uint(qpA[8 * QS_PAD + kc + 4]);
#pragma unroll
            for (int j = 0; j < 8; j++) {
                uint32_t b0 = __float_as_uint(kpB[j * 8 * KS_PAD + kc]);
                uint32_t b1 = __float_as_uint(kpB[j * 8 * KS_PAD + kc + 4]);
                mma_tf32(sacc[j][0], sacc[j][1], sacc[j][2], sacc[j][3],
                         a0, a1, a2, a3, b0, b1);
            }
        }

        // ---- partial row max (causal via predicate) ----
        float pmax_lo = NEG_BIG, pmax_hi = NEG_BIG;
#pragma unroll
        for (int j = 0; j < 8; j++) {
            int c0 = n0 + j * 8 + 2 * tig;
            if (c0     <= r_lo + doff) pmax_lo = fmaxf(pmax_lo, sacc[j][0]);
            if (c0 + 1 <= r_lo + doff) pmax_lo = fmaxf(pmax_lo, sacc[j][1]);
            if (c0     <= r_hi + doff) pmax_hi = fmaxf(pmax_hi, sacc[j][2]);
            if (c0 + 1 <= r_hi + doff) pmax_hi = fmaxf(pmax_hi, sacc[j][3]);
        }
        pmax_lo = fmaxf(pmax_lo, __shfl_xor_sync(0xFFFFFFFF, pmax_lo, 1));
        pmax_lo = fmaxf(pmax_lo, __shfl_xor_sync(0xFFFFFFFF, pmax_lo, 2));
        pmax_hi = fmaxf(pmax_hi, __shfl_xor_sync(0xFFFFFFFF, pmax_hi, 1));
        pmax_hi = fmaxf(pmax_hi, __shfl_xor_sync(0xFFFFFFFF, pmax_hi, 2));
        if (tig == 0) {
            pm[half * 64 + r_lo] = pmax_lo;
            pm[half * 64 + r_hi] = pmax_hi;
        }
        __syncthreads();

        // ---- combine halves, exp, partial sums, store P ----
        float mn_lo = fmaxf(m_lo, fmaxf(pm[r_lo], pm[64 + r_lo]));
        float mn_hi = fmaxf(m_hi, fmaxf(pm[r_hi], pm[64 + r_hi]));
        float al_lo = __expf(m_lo - mn_lo);
        float al_hi = __expf(m_hi - mn_hi);
        m_lo = mn_lo; m_hi = mn_hi;

        float sum_lo = 0.f, sum_hi = 0.f;
#pragma unroll
        for (int j = 0; j < 8; j++) {
            int c0 = n0 + j * 8 + 2 * tig;
            float p0 = (c0     <= r_lo + doff) ? __expf(sacc[j][0] - mn_lo) : 0.f;
            float p1 = (c0 + 1 <= r_lo + doff) ? __expf(sacc[j][1] - mn_lo) : 0.f;
            float p2 = (c0     <= r_hi + doff) ? __expf(sacc[j][2] - mn_hi) : 0.f;
            float p3 = (c0 + 1 <= r_hi + doff) ? __expf(sacc[j][3] - mn_hi) : 0.f;
            sum_lo += p0 + p1;
            sum_hi += p2 + p3;
            float2 v01; v01.x = tf32r(p0); v01.y = tf32r(p1);
            float2 v23; v23.x = tf32r(p2); v23.y = tf32r(p3);
            *(float2*)(Ps + r_lo * PS_PAD + c0) = v01;
            *(float2*)(Ps + r_hi * PS_PAD + c0) = v23;
        }
        sum_lo += __shfl_xor_sync(0xFFFFFFFF, sum_lo, 1);
        sum_lo += __shfl_xor_sync(0xFFFFFFFF, sum_lo, 2);
        sum_hi += __shfl_xor_sync(0xFFFFFFFF, sum_hi, 1);
        sum_hi += __shfl_xor_sync(0xFFFFFFFF, sum_hi, 2);
        if (tig == 0) {
            pl[half * 64 + r_lo] = sum_lo;
            pl[half * 64 + r_hi] = sum_hi;
        }
        __syncthreads();

        // ---- l update, O rescale, PV mma on this warp's d half ----
        l_lo = l_lo * al_lo + pl[r_lo] + pl[64 + r_lo];
        l_hi = l_hi * al_hi + pl[r_hi] + pl[64 + r_hi];
#pragma unroll
        for (int j = 0; j < 8; j++) {
            oacc[j][0] *= al_lo; oacc[j][1] *= al_lo;
            oacc[j][2] *= al_hi; oacc[j][3] *= al_hi;
        }

        const float* ppA = Ps + r_lo * PS_PAD;
#pragma unroll 4
        for (int ks = 0; ks < 16; ks++) {
            int kc = ks * 8 + tig;
            uint32_t a0 = __float_as_uint(ppA[kc]);
            uint32_t a1 = __float_as_uint(ppA[8 * PS_PAD + kc]);
            uint32_t a2 = __float_as_uint(ppA[kc + 4]);
            uint32_t a3 = __float_as_uint(ppA[8 * PS_PAD + kc + 4]);
            const float* vpB = Vs + kc * VS_PAD + n0 + grp;
#pragma unroll
            for (int j = 0; j < 8; j++) {
                uint32_t b0 = __float_as_uint(vpB[j * 8]);
                uint32_t b1 = __float_as_uint(vpB[4 * VS_PAD + j * 8]);
                mma_tf32(oacc[j][0], oacc[j][1], oacc[j][2], oacc[j][3],
                         a0, a1, a2, a3, b0, b1);
            }
        }
    }

    // ---- normalize + store (tf32-rounded so out-proj input is pre-rounded) ----
    float inv_lo = 1.f / l_lo;
    float inv_hi = 1.f / l_hi;
    float* obase = out + (size_t)(b * SEQ + qrow0) * DMODEL + h * DHEAD;
#pragma unroll
    for (int j = 0; j < 8; j++) {
        int col = n0 + j * 8 + 2 * tig;
        float2 o0, o1;
        o0.x = tf32r(oacc[j][0] * inv_lo); o0.y = tf32r(oacc[j][1] * inv_lo);
        o1.x = tf32r(oacc[j][2] * inv_hi); o1.y = tf32r(oacc[j][3] * inv_hi);
        *(float2*)(obase + (size_t)r_lo * DMODEL + col) = o0;
        *(float2*)(obase + (size_t)r_hi * DMODEL + col) = o1;
    }
}

// ===========================================================================
// Launch
// ===========================================================================
extern "C" void kernel_launch(void* const* d_in, const int* in_sizes, int n_in,
                              void* d_out, int out_size) {
    const float* x     = (const float*)d_in[0];
    const float* w_in  = (const float*)d_in[2];
    const float* b_in  = (const float*)d_in[3];
    const float* w_out = (const float*)d_in[4];
    const float* b_out = (const float*)d_in[5];
    float* out = (float*)d_out;

    float* qkv;   cudaGetSymbolAddress((void**)&qkv,  g_qkv);
    float* attn;  cudaGetSymbolAddress((void**)&attn, g_attn);

    cudaFuncSetAttribute(attn_mma_kernel,
                         cudaFuncAttributeMaxDynamicSharedMemorySize,
                         ATT_SMEM_FLOATS * (int)sizeof(float));
    cudaFuncSetAttribute(mma_gemm_kernel,
                         cudaFuncAttributeMaxDynamicSharedMemorySize,
                         GEMM_SMEM);

    // 1. RoPE tables
    rope_table_kernel<<<(SEQ * 64 + 255) / 256, 256>>>();

    // 2. QKV projection (mma.sync tf32)
    mma_gemm_kernel<<<dim3(D3 / 128, (BATCH * SEQ) / 128), 256, GEMM_SMEM>>>(
        x, w_in, b_in, qkv, D3);

    // 3. RoPE + attention input pre-round/prescale
    rope_apply_kernel<<<(BATCH * SEQ * NHEAD * 64) / 256, 256>>>();

    // 4. Flash attention (mma.sync tf32)
    attn_mma_kernel<<<dim3(SEQ / 64, NHEAD, BATCH), 256,
                      ATT_SMEM_FLOATS * sizeof(float)>>>(qkv, attn);

    // 5. Output projection (mma.sync tf32)
    mma_gemm_kernel<<<dim3(DMODEL / 128, (BATCH * SEQ) / 128), 256, GEMM_SMEM>>>(
        attn, w_out, b_out, out, DMODEL);
}

// round 10
// speedup vs baseline: 1.4027x; 1.0426x over previous
#include <cuda_runtime.h>
#include <math.h>
#include <stdint.h>

#define BATCH 2
#define SEQ   2048
#define DMODEL 2048
#define NHEAD 16
#define DHEAD 128
#define D3    (3*DMODEL)
#define KDIM  2048

// Scratch (device globals — no allocation allowed)
__device__ float g_qkv[(size_t)BATCH * SEQ * D3];        // [B,S,3D]
__device__ float g_attn[(size_t)BATCH * SEQ * DMODEL];   // [B,S,D]
__device__ float g_cos[SEQ * 64];
__device__ float g_sin[SEQ * 64];

__device__ __forceinline__ uint32_t f2tf32(float x) {
    uint32_t r;
    asm("cvt.rna.tf32.f32 %0, %1;" : "=r"(r) : "f"(x));
    return r;
}
__device__ __forceinline__ float tf32r(float x) {
    float r;
    asm("cvt.rna.tf32.f32 %0, %1;" : "=f"(r) : "f"(x));
    return r;
}

__device__ __forceinline__ void mma_tf32(float& d0, float& d1, float& d2, float& d3,
                                         uint32_t a0, uint32_t a1, uint32_t a2, uint32_t a3,
                                         uint32_t b0, uint32_t b1) {
    asm volatile(
        "mma.sync.aligned.m16n8k8.row.col.f32.tf32.tf32.f32 "
        "{%0,%1,%2,%3}, {%4,%5,%6,%7}, {%8,%9}, {%0,%1,%2,%3};"
        : "+f"(d0), "+f"(d1), "+f"(d2), "+f"(d3)
        : "r"(a0), "r"(a1), "r"(a2), "r"(a3), "r"(b0), "r"(b1));
}

// ===========================================================================
// mma.sync tf32 GEMM (round-7 exact — known good)
// ===========================================================================
#define BK 32
#define NT (KDIM / BK)
#define AS 36
#define BS 136
#define A_STG (128 * AS)
#define B_STG (32 * BS)
#define STG_FLOATS (A_STG + B_STG)
#define GEMM_SMEM (2 * STG_FLOATS * 4)

__global__ void __launch_bounds__(256, 1)
mma_gemm_kernel(const float* __restrict__ A, const float* __restrict__ W,
                const float* __restrict__ bias, float* __restrict__ C, int N) {
    extern __shared__ float smem[];

    const int tid  = threadIdx.x;
    const int lane = tid & 31;
    const int warp = tid >> 5;
    const int wm   = warp >> 1;
    const int wn   = warp & 1;
    const int grp  = lane >> 2;
    const int tig  = lane & 3;
    const int brow = blockIdx.y;
    const int bcol = blockIdx.x;

    const int ar  = tid >> 3;
    const int ac4 = tid & 7;
    const int bk  = tid >> 5;
    const int bc4 = tid & 31;

    const float* Ag = A + (size_t)(brow * 128 + ar) * KDIM + ac4 * 4;
    const float* Wg = W + (size_t)bk * N + bcol * 128 + bc4 * 4;

    float4 bufA[4], bufB[4];

    auto ldg_chunk = [&](int j) {
        int k0 = j * BK;
#pragma unroll
        for (int i = 0; i < 4; i++)
            bufA[i] = *(const float4*)(Ag + (size_t)(i * 32) * KDIM + k0);
#pragma unroll
        for (int i = 0; i < 4; i++)
            bufB[i] = *(const float4*)(Wg + (size_t)(k0 + i * 8) * N);
    };

    auto sts_chunk = [&](int s) {
        float* sa = smem + s * STG_FLOATS;
        float* sb = sa + A_STG;
#pragma unroll
        for (int i = 0; i < 4; i++) {
            uint4 v;
            v.x = f2tf32(bufA[i].x); v.y = f2tf32(bufA[i].y);
            v.z = f2tf32(bufA[i].z); v.w = f2tf32(bufA[i].w);
            *(uint4*)(sa + (ar + i * 32) * AS + ac4 * 4) = v;
        }
#pragma unroll
        for (int i = 0; i < 4; i++) {
            uint4 v;
            v.x = f2tf32(bufB[i].x); v.y = f2tf32(bufB[i].y);
            v.z = f2tf32(bufB[i].z); v.w = f2tf32(bufB[i].w);
            *(uint4*)(sb + (bk + i * 8) * BS + bc4 * 4) = v;
        }
    };

    float acc[2][8][4];
#pragma unroll
    for (int m = 0; m < 2; m++)
#pragma unroll
        for (int n = 0; n < 8; n++)
#pragma unroll
            for (int c = 0; c < 4; c++) acc[m][n][c] = 0.f;

    ldg_chunk(0);
    sts_chunk(0);
    __syncthreads();

    const int rb0 = wm * 32 + grp;
    const int cb0 = wn * 64 + grp;

    for (int j = 0; j < NT; j++) {
        if (j + 1 < NT) ldg_chunk(j + 1);

        const float* sa = smem + (j & 1) * STG_FLOATS;
        const float* sb = sa + A_STG;
#pragma unroll
        for (int ks = 0; ks < 4; ks++) {
            int kc = ks * 8 + tig;
            uint32_t af[2][4];
#pragma unroll
            for (int m = 0; m < 2; m++) {
                const float* ap = sa + (rb0 + m * 16) * AS + kc;
                af[m][0] = __float_as_uint(ap[0]);
                af[m][1] = __float_as_uint(ap[8 * AS]);
                af[m][2] = __float_as_uint(ap[4]);
                af[m][3] = __float_as_uint(ap[8 * AS + 4]);
            }
            uint32_t bf[8][2];
            const float* bp = sb + kc * BS + cb0;
#pragma unroll
            for (int n = 0; n < 8; n++) {
                bf[n][0] = __float_as_uint(bp[n * 8]);
                bf[n][1] = __float_as_uint(bp[4 * BS + n * 8]);
            }
#pragma unroll
            for (int m = 0; m < 2; m++)
#pragma unroll
                for (int n = 0; n < 8; n++)
                    mma_tf32(acc[m][n][0], acc[m][n][1], acc[m][n][2], acc[m][n][3],
                             af[m][0], af[m][1], af[m][2], af[m][3],
                             bf[n][0], bf[n][1]);
        }

        if (j + 1 < NT) sts_chunk((j + 1) & 1);
        __syncthreads();
    }

#pragma unroll
    for (int m = 0; m < 2; m++) {
        int row0 = brow * 128 + wm * 32 + m * 16 + grp;
#pragma unroll
        for (int n = 0; n < 8; n++) {
            int col = bcol * 128 + wn * 64 + n * 8 + tig * 2;
            float2 bv = *(const float2*)(bias + col);
            float2 o0, o1;
            o0.x = acc[m][n][0] + bv.x; o0.y = acc[m][n][1] + bv.y;
            o1.x = acc[m][n][2] + bv.x; o1.y = acc[m][n][3] + bv.y;
            *(float2*)(C + (size_t)row0 * N + col)       = o0;
            *(float2*)(C + (size_t)(row0 + 8) * N + col) = o1;
        }
    }
}

// ===========================================================================
// RoPE (pre-bakes attention input conversions)
// ===========================================================================
__global__ void rope_table_kernel() {
    int idx = blockIdx.x * blockDim.x + threadIdx.x;
    if (idx >= SEQ * 64) return;
    int s = idx >> 6;
    int i = idx & 63;
    double theta = exp(-(double)i * log(10000.0) / 64.0);
    float tf = (float)theta;
    float ang = (float)s * tf;
    g_cos[idx] = (float)cos((double)ang);
    g_sin[idx] = (float)sin((double)ang);
}

__global__ void rope_apply_kernel() {
    const float SCALE = 0.08838834764831845f;  // 1/sqrt(128)
    int idx = blockIdx.x * blockDim.x + threadIdx.x;
    int i = idx & 63;
    int h = (idx >> 6) & (NHEAD - 1);
    int s = (idx >> 10) & (SEQ - 1);
    int b = idx >> 21;
    if (b >= BATCH) return;

    float c  = g_cos[s * 64 + i];
    float sn = g_sin[s * 64 + i];

    size_t base = ((size_t)(b * SEQ + s)) * D3 + h * DHEAD;
    float* q = g_qkv + base;
    float* k = g_qkv + base + DMODEL;
    float* v = g_qkv + base + 2 * DMODEL;

    float q0 = q[i], q1 = q[i + 64];
    q[i]      = tf32r(SCALE * (c * q0 - sn * q1));
    q[i + 64] = tf32r(SCALE * (c * q1 + sn * q0));

    float k0 = k[i], k1 = k[i + 64];
    k[i]      = tf32r(c * k0 - sn * k1);
    k[i + 64] = tf32r(c * k1 + sn * k0);

    v[i]      = tf32r(v[i]);
    v[i + 64] = tf32r(v[i + 64]);
}

// ===========================================================================
// Flash attention, warp-local softmax.
// CTA: 128 q-rows (8 warps x 16 rows), kv-tile 64 keys.
// Each warp owns FULL score rows -> softmax needs only quad shfl + __syncwarp;
// only the K/V tile load uses __syncthreads (2 per iteration).
// Pads: Q/K 132, V 136, P 68 (per-warp private) — all frag reads conflict-free.
// ===========================================================================
#define ATQ_PAD 132
#define ATK_PAD 132
#define ATV_PAD 136
#define ATP_PAD 68
#define ATQ_OFF 0
#define ATK_OFF (128 * ATQ_PAD)                 // 16896
#define ATV_OFF (ATK_OFF + 64 * ATK_PAD)        // 25344
#define ATP_OFF (ATV_OFF + 64 * ATV_PAD)        // 34048
#define ATT_SMEM_FLOATS (ATP_OFF + 8 * 16 * ATP_PAD)  // 42752 floats = 171008 B

__global__ void __launch_bounds__(256, 1)
attn_mma_kernel(const float* __restrict__ qkv, float* __restrict__ out) {
    extern __shared__ float sm[];
    float* Qs = sm + ATQ_OFF;
    float* Ks = sm + ATK_OFF;
    float* Vs = sm + ATV_OFF;

    const float NEG_BIG = -3.0e38f;

    const int qt = (int)gridDim.x - 1 - (int)blockIdx.x;  // heavy tiles first
    const int h = blockIdx.y, b = blockIdx.z;
    const int tid = threadIdx.x;
    const int lane = tid & 31, warp = tid >> 5;
    const int grp = lane >> 2, tig = lane & 3;

    float* Pw = sm + ATP_OFF + warp * (16 * ATP_PAD);  // per-warp private

    const float* qbase = qkv + (size_t)(b * SEQ) * D3 + h * DHEAD;
    const float* kbase = qbase + DMODEL;
    const float* vbase = qbase + 2 * DMODEL;

    const int qrow0 = qt * 128;
    const int r_lo = warp * 16 + grp;
    const int r_hi = r_lo + 8;

    // Load Q tile [128][128] (pre-scaled + rounded by rope pass)
#pragma unroll
    for (int t = 0; t < 16; t++) {
        int lin = tid + t * 256;
        int row = lin >> 5;
        int d0 = (lin & 31) * 4;
        float4 v = *(const float4*)(qbase + (size_t)(qrow0 + row) * D3 + d0);
        *(float4*)(Qs + row * ATQ_PAD + d0) = v;
    }

    float oacc[16][4];
#pragma unroll
    for (int j = 0; j < 16; j++)
#pragma unroll
        for (int c = 0; c < 4; c++) oacc[j][c] = 0.f;

    float m_lo = NEG_BIG, m_hi = NEG_BIG;
    float l_lo = 0.f, l_hi = 0.f;

    const int nkt = 2 * qt + 2;

    for (int kt = 0; kt < nkt; kt++) {
        const int key0 = kt * 64;
        const int doff = qrow0 - key0;

        __syncthreads();   // previous tile fully consumed (covers Q on kt=0)

        // Load K,V tile [64][128]
#pragma unroll
        for (int t = 0; t < 8; t++) {
            int lin = tid + t * 256;
            int row = lin >> 5;
            int d0 = (lin & 31) * 4;
            size_t goff = (size_t)(key0 + row) * D3 + d0;
            *(float4*)(Ks + row * ATK_PAD + d0) = *(const float4*)(kbase + goff);
            *(float4*)(Vs + row * ATV_PAD + d0) = *(const float4*)(vbase + goff);
        }
        __syncthreads();

        // ---- S = Q @ K^T : warp's 16 rows x all 64 keys ----
        float sacc[8][4];
#pragma unroll
        for (int j = 0; j < 8; j++)
#pragma unroll
            for (int c = 0; c < 4; c++) sacc[j][c] = 0.f;

        const float* qpA = Qs + r_lo * ATQ_PAD;
        const float* kpB = Ks + grp * ATK_PAD;
#pragma unroll 4
        for (int ks = 0; ks < 16; ks++) {
            int kc = ks * 8 + tig;
            uint32_t a0 = __float_as_uint(qpA[kc]);
            uint32_t a1 = __float_as_uint(qpA[8 * ATQ_PAD + kc]);
            uint32_t a2 = __float_as_uint(qpA[kc + 4]);
            uint32_t a3 = __float_as_uint(qpA[8 * ATQ_PAD + kc + 4]);
#pragma unroll
            for (int j = 0; j < 8; j++) {
                uint32_t b0 = __float_as_uint(kpB[j * 8 * ATK_PAD + kc]);
                uint32_t b1 = __float_as_uint(kpB[j * 8 * ATK_PAD + kc + 4]);
                mma_tf32(sacc[j][0], sacc[j][1], sacc[j][2], sacc[j][3],
                         a0, a1, a2, a3, b0, b1);
            }
        }

        // ---- warp-local softmax: full-row max via quad shfl ----
        float pmax_lo = NEG_BIG, pmax_hi = NEG_BIG;
#pragma unroll
        for (int j = 0; j < 8; j++) {
            int c0 = j * 8 + 2 * tig;
            if (c0     <= r_lo + doff) pmax_lo = fmaxf(pmax_lo, sacc[j][0]);
            if (c0 + 1 <= r_lo + doff) pmax_lo = fmaxf(pmax_lo, sacc[j][1]);
            if (c0     <= r_hi + doff) pmax_hi = fmaxf(pmax_hi, sacc[j][2]);
            if (c0 + 1 <= r_hi + doff) pmax_hi = fmaxf(pmax_hi, sacc[j][3]);
        }
        pmax_lo = fmaxf(pmax_lo, __shfl_xor_sync(0xFFFFFFFF, pmax_lo, 1));
        pmax_lo = fmaxf(pmax_lo, __shfl_xor_sync(0xFFFFFFFF, pmax_lo, 2));
        pmax_hi = fmaxf(pmax_hi, __shfl_xor_sync(0xFFFFFFFF, pmax_hi, 1));
        pmax_hi = fmaxf(pmax_hi, __shfl_xor_sync(0xFFFFFFFF, pmax_hi, 2));

        float mn_lo = fmaxf(m_lo, pmax_lo);
        float mn_hi = fmaxf(m_hi, pmax_hi);
        float al_lo = __expf(m_lo - mn_lo);
        float al_hi = __expf(m_hi - mn_hi);
        m_lo = mn_lo; m_hi = mn_hi;

        // exp + partial sums + store P (warp-private region)
        float sum_lo = 0.f, sum_hi = 0.f;
#pragma unroll
        for (int j = 0; j < 8; j++) {
            int c0 = j * 8 + 2 * tig;
            float p0 = (c0     <= r_lo + doff) ? __expf(sacc[j][0] - mn_lo) : 0.f;
            float p1 = (c0 + 1 <= r_lo + doff) ? __expf(sacc[j][1] - mn_lo) : 0.f;
            float p2 = (c0     <= r_hi + doff) ? __expf(sacc[j][2] - mn_hi) : 0.f;
            float p3 = (c0 + 1 <= r_hi + doff) ? __expf(sacc[j][3] - mn_hi) : 0.f;
            sum_lo += p0 + p1;
            sum_hi += p2 + p3;
            float2 v01; v01.x = tf32r(p0); v01.y = tf32r(p1);
            float2 v23; v23.x = tf32r(p2); v23.y = tf32r(p3);
            *(float2*)(Pw + grp * ATP_PAD + c0)       = v01;
            *(float2*)(Pw + (grp + 8) * ATP_PAD + c0) = v23;
        }
        sum_lo += __shfl_xor_sync(0xFFFFFFFF, sum_lo, 1);
        sum_lo += __shfl_xor_sync(0xFFFFFFFF, sum_lo, 2);
        sum_hi += __shfl_xor_sync(0xFFFFFFFF, sum_hi, 1);
        sum_hi += __shfl_xor_sync(0xFFFFFFFF, sum_hi, 2);

        l_lo = l_lo * al_lo + sum_lo;
        l_hi = l_hi * al_hi + sum_hi;

        // rescale O
#pragma unroll
        for (int j = 0; j < 16; j++) {
            oacc[j][0] *= al_lo; oacc[j][1] *= al_lo;
            oacc[j][2] *= al_hi; oacc[j][3] *= al_hi;
        }
        __syncwarp();   // P visible within warp

        // ---- O += P @ V : warp's 16 rows x full 128 d ----
#pragma unroll 2
        for (int ks = 0; ks < 8; ks++) {
            int kc = ks * 8 + tig;
            uint32_t a0 = __float_as_uint(Pw[grp * ATP_PAD + kc]);
            uint32_t a1 = __float_as_uint(Pw[(grp + 8) * ATP_PAD + kc]);
            uint32_t a2 = __float_as_uint(Pw[grp * ATP_PAD + kc + 4]);
            uint32_t a3 = __float_as_uint(Pw[(grp + 8) * ATP_PAD + kc + 4]);
            const float* vp0 = Vs + kc * ATV_PAD + grp;
            const float* vp1 = Vs + (kc + 4) * ATV_PAD + grp;
#pragma unroll
            for (int j = 0; j < 16; j++) {
                uint32_t b0 = __float_as_uint(vp0[j * 8]);
                uint32_t b1 = __float_as_uint(vp1[j * 8]);
                mma_tf32(oacc[j][0], oacc[j][1], oacc[j][2], oacc[j][3],
                         a0, a1, a2, a3, b0, b1);
            }
        }
    }

    // ---- normalize + store ----
    float inv_lo = 1.f / l_lo;
    float inv_hi = 1.f / l_hi;
    float* obase = out + (size_t)(b * SEQ + qrow0) * DMODEL + h * DHEAD;
#pragma unroll
    for (int j = 0; j < 16; j++) {
        int col = j * 8 + 2 * tig;
        float2 o0, o1;
        o0.x = oacc[j][0] * inv_lo; o0.y = oacc[j][1] * inv_lo;
        o1.x = oacc[j][2] * inv_hi; o1.y = oacc[j][3] * inv_hi;
        *(float2*)(obase + (size_t)r_lo * DMODEL + col) = o0;
        *(float2*)(obase + (size_t)r_hi * DMODEL + col) = o1;
    }
}

// ===========================================================================
// Launch
// ===========================================================================
extern "C" void kernel_launch(void* const* d_in, const int* in_sizes, int n_in,
                              void* d_out, int out_size) {
    const float* x     = (const float*)d_in[0];
    const float* w_in  = (const float*)d_in[2];
    const float* b_in  = (const float*)d_in[3];
    const float* w_out = (const float*)d_in[4];
    const float* b_out = (const float*)d_in[5];
    float* out = (float*)d_out;

    float* qkv;   cudaGetSymbolAddress((void**)&qkv,  g_qkv);
    float* attn;  cudaGetSymbolAddress((void**)&attn, g_attn);

    cudaFuncSetAttribute(attn_mma_kernel,
                         cudaFuncAttributeMaxDynamicSharedMemorySize,
                         ATT_SMEM_FLOATS * (int)sizeof(float));
    cudaFuncSetAttribute(mma_gemm_kernel,
                         cudaFuncAttributeMaxDynamicSharedMemorySize,
                         GEMM_SMEM);

    // 1. RoPE tables
    rope_table_kernel<<<(SEQ * 64 + 255) / 256, 256>>>();

    // 2. QKV projection (mma.sync tf32)
    mma_gemm_kernel<<<dim3(D3 / 128, (BATCH * SEQ) / 128), 256, GEMM_SMEM>>>(
        x, w_in, b_in, qkv, D3);

    // 3. RoPE + attention input pre-round/prescale
    rope_apply_kernel<<<(BATCH * SEQ * NHEAD * 64) / 256, 256>>>();

    // 4. Flash attention (warp-local softmax, mma.sync tf32)
    attn_mma_kernel<<<dim3(SEQ / 128, NHEAD, BATCH), 256,
                      ATT_SMEM_FLOATS * sizeof(float)>>>(qkv, attn);

    // 5. Output projection (mma.sync tf32)
    mma_gemm_kernel<<<dim3(DMODEL / 128, (BATCH * SEQ) / 128), 256, GEMM_SMEM>>>(
        attn, w_out, b_out, out, DMODEL);
}

// round 11
// speedup vs baseline: 1.4135x; 1.0077x over previous
#include <cuda_runtime.h>
#include <math.h>
#include <stdint.h>

#define BATCH 2
#define SEQ   2048
#define DMODEL 2048
#define NHEAD 16
#define DHEAD 128
#define D3    (3*DMODEL)
#define KDIM  2048

// Scratch (device globals — no allocation allowed)
__device__ float g_qkv[(size_t)BATCH * SEQ * D3];        // [B,S,3D]
__device__ float g_attn[(size_t)BATCH * SEQ * DMODEL];   // [B,S,D]
__device__ float g_cos[SEQ * 64];
__device__ float g_sin[SEQ * 64];

__device__ __forceinline__ uint32_t f2tf32(float x) {
    uint32_t r;
    asm("cvt.rna.tf32.f32 %0, %1;" : "=r"(r) : "f"(x));
    return r;
}
__device__ __forceinline__ float tf32r(float x) {
    float r;
    asm("cvt.rna.tf32.f32 %0, %1;" : "=f"(r) : "f"(x));
    return r;
}

__device__ __forceinline__ void mma_tf32(float& d0, float& d1, float& d2, float& d3,
                                         uint32_t a0, uint32_t a1, uint32_t a2, uint32_t a3,
                                         uint32_t b0, uint32_t b1) {
    asm volatile(
        "mma.sync.aligned.m16n8k8.row.col.f32.tf32.tf32.f32 "
        "{%0,%1,%2,%3}, {%4,%5,%6,%7}, {%8,%9}, {%0,%1,%2,%3};"
        : "+f"(d0), "+f"(d1), "+f"(d2), "+f"(d3)
        : "r"(a0), "r"(a1), "r"(a2), "r"(a3), "r"(b0), "r"(b1));
}

// ===========================================================================
// mma.sync tf32 GEMM, BK=64 (half the chunks/barriers of the BK=32 version).
// CTA tile 128x128, 256 threads (8 warps: 4m x 2n, warp 32x64).
//   A smem [128][AS2=68]  (68 mod 32 = 4 -> bank 4*grp+tig, conflict-free)
//   B smem [64][BS2=136]  (bank 8*tig+grp, conflict-free)
// Ldg/sts split into halves interleaved with compute -> staging stays 8xfloat4.
// ===========================================================================
#define BK2 64
#define NT2 (KDIM / BK2)          // 32
#define AS2 68
#define BS2 136
#define A_STG2 (128 * AS2)        // 8704 floats
#define B_STG2 (64 * BS2)         // 8704 floats
#define STG2 (A_STG2 + B_STG2)    // 17408 floats
#define GEMM_SMEM (2 * STG2 * 4)  // 139264 B

__global__ void __launch_bounds__(256, 1)
mma_gemm_kernel(const float* __restrict__ A, const float* __restrict__ W,
                const float* __restrict__ bias, float* __restrict__ C, int N) {
    extern __shared__ float smem[];

    const int tid  = threadIdx.x;
    const int lane = tid & 31;
    const int warp = tid >> 5;
    const int wm   = warp >> 1;
    const int wn   = warp & 1;
    const int grp  = lane >> 2;
    const int tig  = lane & 3;
    const int brow = blockIdx.y;
    const int bcol = blockIdx.x;

    // loader indices (A: 16 float4/row; B: 32 float4/row)
    const int arow  = tid >> 4;   // + i*16
    const int acol4 = tid & 15;
    const int bkrow = tid >> 5;   // + i*8
    const int bcol4 = tid & 31;

    const float* Ag = A + (size_t)(brow * 128 + arow) * KDIM + acol4 * 4;
    const float* Wg = W + (size_t)bkrow * N + bcol * 128 + bcol4 * 4;

    float4 bufA[4], bufB[4];

    auto ldg_half = [&](int j, int h) {
        int k0 = j * BK2;
#pragma unroll
        for (int t = 0; t < 4; t++) {
            int i = h * 4 + t;
            bufA[t] = *(const float4*)(Ag + (size_t)(i * 16) * KDIM + k0);
            bufB[t] = *(const float4*)(Wg + (size_t)(k0 + i * 8) * N);
        }
    };

    auto sts_half = [&](int s, int h) {
        float* sa = smem + s * STG2;
        float* sb = sa + A_STG2;
#pragma unroll
        for (int t = 0; t < 4; t++) {
            int i = h * 4 + t;
            uint4 va;
            va.x = f2tf32(bufA[t].x); va.y = f2tf32(bufA[t].y);
            va.z = f2tf32(bufA[t].z); va.w = f2tf32(bufA[t].w);
            *(uint4*)(sa + (arow + i * 16) * AS2 + acol4 * 4) = va;
            uint4 vb;
            vb.x = f2tf32(bufB[t].x); vb.y = f2tf32(bufB[t].y);
            vb.z = f2tf32(bufB[t].z); vb.w = f2tf32(bufB[t].w);
            *(uint4*)(sb + (bkrow + i * 8) * BS2 + bcol4 * 4) = vb;
        }
    };

    float acc[2][8][4];
#pragma unroll
    for (int m = 0; m < 2; m++)
#pragma unroll
        for (int n = 0; n < 8; n++)
#pragma unroll
            for (int c = 0; c < 4; c++) acc[m][n][c] = 0.f;

    const int rb0 = wm * 32 + grp;
    const int cb0 = wn * 64 + grp;

    auto compute_half = [&](int s, int h) {
        const float* sa = smem + s * STG2;
        const float* sb = sa + A_STG2;
#pragma unroll
        for (int ks = 0; ks < 4; ks++) {
            int kc = (h * 4 + ks) * 8 + tig;
            uint32_t af[2][4];
#pragma unroll
            for (int m = 0; m < 2; m++) {
                const float* ap = sa + (rb0 + m * 16) * AS2 + kc;
                af[m][0] = __float_as_uint(ap[0]);
                af[m][1] = __float_as_uint(ap[8 * AS2]);
                af[m][2] = __float_as_uint(ap[4]);
                af[m][3] = __float_as_uint(ap[8 * AS2 + 4]);
            }
            uint32_t bf[8][2];
            const float* bp = sb + kc * BS2 + cb0;
#pragma unroll
            for (int n = 0; n < 8; n++) {
                bf[n][0] = __float_as_uint(bp[n * 8]);
                bf[n][1] = __float_as_uint(bp[4 * BS2 + n * 8]);
            }
#pragma unroll
            for (int m = 0; m < 2; m++)
#pragma unroll
                for (int n = 0; n < 8; n++)
                    mma_tf32(acc[m][n][0], acc[m][n][1], acc[m][n][2], acc[m][n][3],
                             af[m][0], af[m][1], af[m][2], af[m][3],
                             bf[n][0], bf[n][1]);
        }
    };

    // preamble: fill stage 0
    ldg_half(0, 0); sts_half(0, 0);
    ldg_half(0, 1); sts_half(0, 1);
    __syncthreads();

    for (int j = 0; j < NT2; j++) {
        const int cur = j & 1;
        const int nxt = cur ^ 1;
        const bool pre = (j + 1 < NT2);

        if (pre) ldg_half(j + 1, 0);
        compute_half(cur, 0);
        if (pre) { sts_half(nxt, 0); ldg_half(j + 1, 1); }
        compute_half(cur, 1);
        if (pre) sts_half(nxt, 1);
        __syncthreads();
    }

    // Epilogue
#pragma unroll
    for (int m = 0; m < 2; m++) {
        int row0 = brow * 128 + wm * 32 + m * 16 + grp;
#pragma unroll
        for (int n = 0; n < 8; n++) {
            int col = bcol * 128 + wn * 64 + n * 8 + tig * 2;
            float2 bv = *(const float2*)(bias + col);
            float2 o0, o1;
            o0.x = acc[m][n][0] + bv.x; o0.y = acc[m][n][1] + bv.y;
            o1.x = acc[m][n][2] + bv.x; o1.y = acc[m][n][3] + bv.y;
            *(float2*)(C + (size_t)row0 * N + col)       = o0;
            *(float2*)(C + (size_t)(row0 + 8) * N + col) = o1;
        }
    }
}

// ===========================================================================
// RoPE
// ===========================================================================
__global__ void rope_table_kernel() {
    int idx = blockIdx.x * blockDim.x + threadIdx.x;
    if (idx >= SEQ * 64) return;
    int s = idx >> 6;
    int i = idx & 63;
    double theta = exp(-(double)i * log(10000.0) / 64.0);
    float tf = (float)theta;
    float ang = (float)s * tf;
    float sv, cv;
    sincosf(ang, &sv, &cv);
    g_cos[idx] = cv;
    g_sin[idx] = sv;
}

__global__ void rope_apply_kernel() {
    const float SCALE = 0.08838834764831845f;  // 1/sqrt(128)
    int idx = blockIdx.x * blockDim.x + threadIdx.x;
    int i = idx & 63;
    int h = (idx >> 6) & (NHEAD - 1);
    int s = (idx >> 10) & (SEQ - 1);
    int b = idx >> 21;
    if (b >= BATCH) return;

    float c  = g_cos[s * 64 + i];
    float sn = g_sin[s * 64 + i];

    size_t base = ((size_t)(b * SEQ + s)) * D3 + h * DHEAD;
    float* q = g_qkv + base;
    float* k = g_qkv + base + DMODEL;
    float* v = g_qkv + base + 2 * DMODEL;

    float q0 = q[i], q1 = q[i + 64];
    q[i]      = tf32r(SCALE * (c * q0 - sn * q1));
    q[i + 64] = tf32r(SCALE * (c * q1 + sn * q0));

    float k0 = k[i], k1 = k[i + 64];
    k[i]      = tf32r(c * k0 - sn * k1);
    k[i + 64] = tf32r(c * k1 + sn * k0);

    v[i]      = tf32r(v[i]);
    v[i + 64] = tf32r(v[i + 64]);
}

// ===========================================================================
// Flash attention, warp-local softmax (round-10 known-good).
// CTA: 128 q-rows (8 warps x 16 rows), kv-tile 64 keys.
// ===========================================================================
#define ATQ_PAD 132
#define ATK_PAD 132
#define ATV_PAD 136
#define ATP_PAD 68
#define ATQ_OFF 0
#define ATK_OFF (128 * ATQ_PAD)
#define ATV_OFF (ATK_OFF + 64 * ATK_PAD)
#define ATP_OFF (ATV_OFF + 64 * ATV_PAD)
#define ATT_SMEM_FLOATS (ATP_OFF + 8 * 16 * ATP_PAD)

__global__ void __launch_bounds__(256, 1)
attn_mma_kernel(const float* __restrict__ qkv, float* __restrict__ out) {
    extern __shared__ float sm[];
    float* Qs = sm + ATQ_OFF;
    float* Ks = sm + ATK_OFF;
    float* Vs = sm + ATV_OFF;

    const float NEG_BIG = -3.0e38f;

    const int qt = (int)gridDim.x - 1 - (int)blockIdx.x;  // heavy tiles first
    const int h = blockIdx.y, b = blockIdx.z;
    const int tid = threadIdx.x;
    const int lane = tid & 31, warp = tid >> 5;
    const int grp = lane >> 2, tig = lane & 3;

    float* Pw = sm + ATP_OFF + warp * (16 * ATP_PAD);

    const float* qbase = qkv + (size_t)(b * SEQ) * D3 + h * DHEAD;
    const float* kbase = qbase + DMODEL;
    const float* vbase = qbase + 2 * DMODEL;

    const int qrow0 = qt * 128;
    const int r_lo = warp * 16 + grp;
    const int r_hi = r_lo + 8;

#pragma unroll
    for (int t = 0; t < 16; t++) {
        int lin = tid + t * 256;
        int row = lin >> 5;
        int d0 = (lin & 31) * 4;
        float4 v = *(const float4*)(qbase + (size_t)(qrow0 + row) * D3 + d0);
        *(float4*)(Qs + row * ATQ_PAD + d0) = v;
    }

    float oacc[16][4];
#pragma unroll
    for (int j = 0; j < 16; j++)
#pragma unroll
        for (int c = 0; c < 4; c++) oacc[j][c] = 0.f;

    float m_lo = NEG_BIG, m_hi = NEG_BIG;
    float l_lo = 0.f, l_hi = 0.f;

    const int nkt = 2 * qt + 2;

    for (int kt = 0; kt < nkt; kt++) {
        const int key0 = kt * 64;
        const int doff = qrow0 - key0;

        __syncthreads();

#pragma unroll
        for (int t = 0; t < 8; t++) {
            int lin = tid + t * 256;
            int row = lin >> 5;
            int d0 = (lin & 31) * 4;
            size_t goff = (size_t)(key0 + row) * D3 + d0;
            *(float4*)(Ks + row * ATK_PAD + d0) = *(const float4*)(kbase + goff);
            *(float4*)(Vs + row * ATV_PAD + d0) = *(const float4*)(vbase + goff);
        }
        __syncthreads();

        float sacc[8][4];
#pragma unroll
        for (int j = 0; j < 8; j++)
#pragma unroll
            for (int c = 0; c < 4; c++) sacc[j][c] = 0.f;

        const float* qpA = Qs + r_lo * ATQ_PAD;
        const float* kpB = Ks + grp * ATK_PAD;
#pragma unroll 4
        for (int ks = 0; ks < 16; ks++) {
            int kc = ks * 8 + tig;
            uint32_t a0 = __float_as_uint(qpA[kc]);
            uint32_t a1 = __float_as_uint(qpA[8 * ATQ_PAD + kc]);
            uint32_t a2 = __float_as_uint(qpA[kc + 4]);
            uint32_t a3 = __float_as_uint(qpA[8 * ATQ_PAD + kc + 4]);
#pragma unroll
            for (int j = 0; j < 8; j++) {
                uint32_t b0 = __float_as_uint(kpB[j * 8 * ATK_PAD + kc]);
                uint32_t b1 = __float_as_uint(kpB[j * 8 * ATK_PAD + kc + 4]);
                mma_tf32(sacc[j][0], sacc[j][1], sacc[j][2], sacc[j][3],
                         a0, a1, a2, a3, b0, b1);
            }
        }

        float pmax_lo = NEG_BIG, pmax_hi = NEG_BIG;
#pragma unroll
        for (int j = 0; j < 8; j++) {
            int c0 = j * 8 + 2 * tig;
            if (c0     <= r_lo + doff) pmax_lo = fmaxf(pmax_lo, sacc[j][0]);
            if (c0 + 1 <= r_lo + doff) pmax_lo = fmaxf(pmax_lo, sacc[j][1]);
            if (c0     <= r_hi + doff) pmax_hi = fmaxf(pmax_hi, sacc[j][2]);
            if (c0 + 1 <= r_hi + doff) pmax_hi = fmaxf(pmax_hi, sacc[j][3]);
        }
        pmax_lo = fmaxf(pmax_lo, __shfl_xor_sync(0xFFFFFFFF, pmax_lo, 1));
        pmax_lo = fmaxf(pmax_lo, __shfl_xor_sync(0xFFFFFFFF, pmax_lo, 2));
        pmax_hi = fmaxf(pmax_hi, __shfl_xor_sync(0xFFFFFFFF, pmax_hi, 1));
        pmax_hi = fmaxf(pmax_hi, __shfl_xor_sync(0xFFFFFFFF, pmax_hi, 2));

        float mn_lo = fmaxf(m_lo, pmax_lo);
        float mn_hi = fmaxf(m_hi, pmax_hi);
        float al_lo = __expf(m_lo - mn_lo);
        float al_hi = __expf(m_hi - mn_hi);
        m_lo = mn_lo; m_hi = mn_hi;

        float sum_lo = 0.f, sum_hi = 0.f;
#pragma unroll
        for (int j = 0; j < 8; j++) {
            int c0 = j * 8 + 2 * tig;
            float p0 = (c0     <= r_lo + doff) ? __expf(sacc[j][0] - mn_lo) : 0.f;
            float p1 = (c0 + 1 <= r_lo + doff) ? __expf(sacc[j][1] - mn_lo) : 0.f;
            float p2 = (c0     <= r_hi + doff) ? __expf(sacc[j][2] - mn_hi) : 0.f;
            float p3 = (c0 + 1 <= r_hi + doff) ? __expf(sacc[j][3] - mn_hi) : 0.f;
            sum_lo += p0 + p1;
            sum_hi += p2 + p3;
            float2 v01; v01.x = tf32r(p0); v01.y = tf32r(p1);
            float2 v23; v23.x = tf32r(p2); v23.y = tf32r(p3);
            *(float2*)(Pw + grp * ATP_PAD + c0)       = v01;
            *(float2*)(Pw + (grp + 8) * ATP_PAD + c0) = v23;
        }
        sum_lo += __shfl_xor_sync(0xFFFFFFFF, sum_lo, 1);
        sum_lo += __shfl_xor_sync(0xFFFFFFFF, sum_lo, 2);
        sum_hi += __shfl_xor_sync(0xFFFFFFFF, sum_hi, 1);
        sum_hi += __shfl_xor_sync(0xFFFFFFFF, sum_hi, 2);

        l_lo = l_lo * al_lo + sum_lo;
        l_hi = l_hi * al_hi + sum_hi;

#pragma unroll
        for (int j = 0; j < 16; j++) {
            oacc[j][0] *= al_lo; oacc[j][1] *= al_lo;
            oacc[j][2] *= al_hi; oacc[j][3] *= al_hi;
        }
        __syncwarp();

#pragma unroll 2
        for (int ks = 0; ks < 8; ks++) {
            int kc = ks * 8 + tig;
            uint32_t a0 = __float_as_uint(Pw[grp * ATP_PAD + kc]);
            uint32_t a1 = __float_as_uint(Pw[(grp + 8) * ATP_PAD + kc]);
            uint32_t a2 = __float_as_uint(Pw[grp * ATP_PAD + kc + 4]);
            uint32_t a3 = __float_as_uint(Pw[(grp + 8) * ATP_PAD + kc + 4]);
            const float* vp0 = Vs + kc * ATV_PAD + grp;
            const float* vp1 = Vs + (kc + 4) * ATV_PAD + grp;
#pragma unroll
            for (int j = 0; j < 16; j++) {
                uint32_t b0 = __float_as_uint(vp0[j * 8]);
                uint32_t b1 = __float_as_uint(vp1[j * 8]);
                mma_tf32(oacc[j][0], oacc[j][1], oacc[j][2], oacc[j][3],
                         a0, a1, a2, a3, b0, b1);
            }
        }
    }

    float inv_lo = 1.f / l_lo;
    float inv_hi = 1.f / l_hi;
    float* obase = out + (size_t)(b * SEQ + qrow0) * DMODEL + h * DHEAD;
#pragma unroll
    for (int j = 0; j < 16; j++) {
        int col = j * 8 + 2 * tig;
        float2 o0, o1;
        o0.x = oacc[j][0] * inv_lo; o0.y = oacc[j][1] * inv_lo;
        o1.x = oacc[j][2] * inv_hi; o1.y = oacc[j][3] * inv_hi;
        *(float2*)(obase + (size_t)r_lo * DMODEL + col) = o0;
        *(float2*)(obase + (size_t)r_hi * DMODEL + col) = o1;
    }
}

// ===========================================================================
// Launch
// ===========================================================================
extern "C" void kernel_launch(void* const* d_in, const int* in_sizes, int n_in,
                              void* d_out, int out_size) {
    const float* x     = (const float*)d_in[0];
    const float* w_in  = (const float*)d_in[2];
    const float* b_in  = (const float*)d_in[3];
    const float* w_out = (const float*)d_in[4];
    const float* b_out = (const float*)d_in[5];
    float* out = (float*)d_out;

    float* qkv;   cudaGetSymbolAddress((void**)&qkv,  g_qkv);
    float* attn;  cudaGetSymbolAddress((void**)&attn, g_attn);

    cudaFuncSetAttribute(attn_mma_kernel,
                         cudaFuncAttributeMaxDynamicSharedMemorySize,
                         ATT_SMEM_FLOATS * (int)sizeof(float));
    cudaFuncSetAttribute(mma_gemm_kernel,
                         cudaFuncAttributeMaxDynamicSharedMemorySize,
                         GEMM_SMEM);

    // 1. RoPE tables
    rope_table_kernel<<<(SEQ * 64 + 255) / 256, 256>>>();

    // 2. QKV projection (mma.sync tf32, BK=64)
    mma_gemm_kernel<<<dim3(D3 / 128, (BATCH * SEQ) / 128), 256, GEMM_SMEM>>>(
        x, w_in, b_in, qkv, D3);

    // 3. RoPE + attention input pre-round/prescale
    rope_apply_kernel<<<(BATCH * SEQ * NHEAD * 64) / 256, 256>>>();

    // 4. Flash attention (warp-local softmax, mma.sync tf32)
    attn_mma_kernel<<<dim3(SEQ / 128, NHEAD, BATCH), 256,
                      ATT_SMEM_FLOATS * sizeof(float)>>>(qkv, attn);

    // 5. Output projection (mma.sync tf32, BK=64)
    mma_gemm_kernel<<<dim3(DMODEL / 128, (BATCH * SEQ) / 128), 256, GEMM_SMEM>>>(
        attn, w_out, b_out, out, DMODEL);
}